// round 4
// baseline (speedup 1.0000x reference)
#include <cuda_runtime.h>

// InteractionBlock: fused
//   d_chi = segment_sum(chi^2)            [n,4]
//   h     = concat(x, d_chi) @ W + b      [n,132]   (W row-major [132,132])
//   a1    = h[:, :128]                    -> out[0 : n*128]
//   chi_out = h[:, 128+seg[m]] * chi[:,m] -> out[n*128 : n*128 + n*16]
//
// Inputs (metadata order): x[n*128] f32, chi[n*16] f32, point_mask[n] (unused),
//                          W[132*132] f32, b[132] f32. Output f32, n*144 elems.

#define TM      128        // rows per CTA
#define KDIM    132        // reduction dim (128 + 4)
#define NCOLS   132        // valid output cols
#define NPAD    144        // padded cols (16 thread-groups * 9)
#define YSTRIDE 133        // padded Y row stride (odd -> bank-conflict-free row groups)
#define THREADS 256

// shared layout (floats)
#define WS_OFF   0
#define WS_SIZE  (KDIM * NPAD)          // 19008
#define YS_OFF   (WS_OFF + WS_SIZE)
#define YS_SIZE  (TM * YSTRIDE)         // 17024
#define CHI_OFF  (YS_OFF + YS_SIZE)
#define CHI_SIZE (TM * 16)              // 2048
#define B_OFF    (CHI_OFF + CHI_SIZE)
#define SMEM_FLOATS (B_OFF + NCOLS)
#define SMEM_BYTES  (SMEM_FLOATS * 4)   // 152,848 B < 227 KB

__global__ __launch_bounds__(THREADS, 1)
void ib_kernel(const float* __restrict__ x,
               const float* __restrict__ chi,
               const float* __restrict__ W,
               const float* __restrict__ b,
               float* __restrict__ out,
               int n)
{
    extern __shared__ float sm[];
    float* Ws = sm + WS_OFF;    // [KDIM][NPAD]
    float* Ys = sm + YS_OFF;    // [TM][YSTRIDE]  (reused as Hs in epilogue)
    float* Ch = sm + CHI_OFF;   // [TM][16]
    float* Bs = sm + B_OFF;     // [NCOLS]

    const int tid = threadIdx.x;
    const long long row0 = (long long)blockIdx.x * TM;

    // ---- stage W (row-major, padded cols) + bias ----
    for (int idx = tid; idx < KDIM * NCOLS; idx += THREADS) {
        int k = idx / NCOLS;
        int j = idx - k * NCOLS;
        Ws[k * NPAD + j] = W[idx];
    }
    if (tid < NCOLS) Bs[tid] = b[tid];

    // ---- stage x tile: Ys[r][k] = x[row0+r][k]  (coalesced float4 loads) ----
    #pragma unroll
    for (int it = 0; it < 16; ++it) {
        int i  = tid + THREADS * it;
        int r  = i >> 5;
        int c4 = (i & 31) << 2;
        long long row = row0 + r;
        float4 v = make_float4(0.f, 0.f, 0.f, 0.f);
        if (row < n) v = *(const float4*)(x + row * 128 + c4);
        float* dst = Ys + r * YSTRIDE + c4;
        dst[0] = v.x; dst[1] = v.y; dst[2] = v.z; dst[3] = v.w;
    }

    // ---- chi: stash + d_chi (segment sums of squares) into Ys[.,128..131] ----
    if (tid < TM) {
        const int r = tid;
        long long row = row0 + r;
        float c[16];
        if (row < n) {
            const float4* cp = (const float4*)(chi + row * 16);
            float4 a0 = cp[0], a1v = cp[1], a2 = cp[2], a3 = cp[3];
            c[0]=a0.x;  c[1]=a0.y;  c[2]=a0.z;  c[3]=a0.w;
            c[4]=a1v.x; c[5]=a1v.y; c[6]=a1v.z; c[7]=a1v.w;
            c[8]=a2.x;  c[9]=a2.y;  c[10]=a2.z; c[11]=a2.w;
            c[12]=a3.x; c[13]=a3.y; c[14]=a3.z; c[15]=a3.w;
        } else {
            #pragma unroll
            for (int m = 0; m < 16; ++m) c[m] = 0.f;
        }
        #pragma unroll
        for (int m = 0; m < 16; ++m) Ch[r * 16 + m] = c[m];
        float d0 = c[0]*c[0];
        float d1 = c[1]*c[1] + c[2]*c[2] + c[3]*c[3];
        float d2 = c[4]*c[4] + c[5]*c[5] + c[6]*c[6] + c[7]*c[7] + c[8]*c[8];
        float d3 = c[9]*c[9] + c[10]*c[10] + c[11]*c[11] + c[12]*c[12]
                 + c[13]*c[13] + c[14]*c[14] + c[15]*c[15];
        float* yd = Ys + r * YSTRIDE + 128;
        yd[0] = d0; yd[1] = d1; yd[2] = d2; yd[3] = d3;
    }
    __syncthreads();

    // ---- 8x9 register-tiled GEMM: 16(ty,row-groups) x 16(tx,col-groups) ----
    const int ty = tid >> 4;          // 0..15
    const int tx = tid & 15;          // 0..15
    const int rbase = ty * 8;
    const int cbase = tx * 9;

    float acc[8][9];
    #pragma unroll
    for (int a = 0; a < 8; ++a)
        #pragma unroll
        for (int q = 0; q < 9; ++q) acc[a][q] = 0.f;

    #pragma unroll 4
    for (int k = 0; k < KDIM; ++k) {
        float yv[8], wv[9];
        #pragma unroll
        for (int a = 0; a < 8; ++a) yv[a] = Ys[(rbase + a) * YSTRIDE + k];
        #pragma unroll
        for (int q = 0; q < 9; ++q) wv[q] = Ws[k * NPAD + cbase + q];
        #pragma unroll
        for (int a = 0; a < 8; ++a)
            #pragma unroll
            for (int q = 0; q < 9; ++q)
                acc[a][q] = fmaf(yv[a], wv[q], acc[a][q]);
    }
    __syncthreads();   // done reading Ys; reuse as H staging

    float* Hs = Ys;    // [TM][YSTRIDE], cols 0..131 valid
    #pragma unroll
    for (int q = 0; q < 9; ++q) {
        int c = cbase + q;
        if (c < NCOLS) {
            float bias = Bs[c];
            #pragma unroll
            for (int a = 0; a < 8; ++a)
                Hs[(rbase + a) * YSTRIDE + c] = acc[a][q] + bias;
        }
    }
    __syncthreads();

    // ---- a1: coalesced float4 stores ----
    float* out1 = out;
    float* out2 = out + (long long)n * 128;
    #pragma unroll
    for (int it = 0; it < 16; ++it) {
        int i  = tid + THREADS * it;
        int r  = i >> 5;
        int c4 = (i & 31) << 2;
        long long row = row0 + r;
        if (row < n) {
            const float* src = Hs + r * YSTRIDE + c4;
            float4 v = make_float4(src[0], src[1], src[2], src[3]);
            *(float4*)(out1 + row * 128 + c4) = v;
        }
    }

    // ---- chi_out: coalesced scalar stores ----
    #pragma unroll
    for (int it = 0; it < 8; ++it) {
        int i = tid + THREADS * it;      // 0 .. 2047
        int r = i >> 4;
        int m = i & 15;
        long long row = row0 + r;
        if (row < n) {
            int s = (m == 0) ? 0 : (m < 4) ? 1 : (m < 9) ? 2 : 3;
            out2[row * 16 + m] = Hs[r * YSTRIDE + 128 + s] * Ch[r * 16 + m];
        }
    }
}

extern "C" void kernel_launch(void* const* d_in, const int* in_sizes, int n_in,
                              void* d_out, int out_size)
{
    const float* x   = (const float*)d_in[0];
    const float* chi = (const float*)d_in[1];
    // d_in[2] = point_mask (unused by the reference computation)
    const float* W   = (const float*)d_in[3];
    const float* b   = (const float*)d_in[4];
    float* out = (float*)d_out;

    const int n = in_sizes[2];   // point_mask element count == n

    cudaFuncSetAttribute(ib_kernel,
                         cudaFuncAttributeMaxDynamicSharedMemorySize,
                         SMEM_BYTES);

    int grid = (n + TM - 1) / TM;
    ib_kernel<<<grid, THREADS, SMEM_BYTES>>>(x, chi, W, b, out, n);
}

// round 6
// speedup vs baseline: 1.6001x; 1.6001x over previous
#include <cuda_runtime.h>
#include <cuda_bf16.h>
#include <cstdint>

// InteractionBlock via warp-level HMMA (mma.sync m16n8k16 bf16, 3-term split):
//   d_chi = segment_sum(chi^2)                          [n,4]
//   h     = x @ W[0:128,:] + d_chi @ W[128:132,:] + b   [n,132]
//   a1      = h[:, :128]        -> out[0 : n*128]
//   chi_out = h[:,128+seg]*chi  -> out[n*128 : n*128+n*16]
//
// GEMM part D[128,144] = A[128,128] @ B[144,128]^T with A,B split into
// bf16 (hi,lo); acc = Ah*Bh + Ah*Bl + Al*Bh (fp32 accumulate).
// The 4 d_chi columns (K tail) are applied exactly in fp32 in the epilogue.
// NOTE: harness ptxas targets plain sm_103 -> no tcgen05/TMEM; mma.sync only.

#define TM        128
#define NPAD      144
#define NCOLS     132
#define THREADS   256
#define ASTRIDE_B 272          // bytes per A row  (136 bf16)
#define BSTRIDE_B 272          // bytes per B row
#define HSTRIDE   148          // floats per H row (mult of 4)

// ---- SMEM byte layout ----
#define SM_A_HI   0
#define A_BYTES   (128*ASTRIDE_B)            // 34816
#define SM_A_LO   (SM_A_HI + A_BYTES)        // 34816
#define SM_B_HI   (SM_A_LO + A_BYTES)        // 69632
#define B_BYTES   (NPAD*BSTRIDE_B)           // 39168
#define SM_B_LO   (SM_B_HI + B_BYTES)        // 108800
#define SM_WT     (SM_B_LO + B_BYTES)        // 147968  (4 x 144 f32)
#define SM_BIAS   (SM_WT + 4*NPAD*4)         // 150272  (144 f32)
#define SM_DCHI   (SM_BIAS + NPAD*4)         // 150848  (128 x 4 f32)
#define SM_CHI    (SM_DCHI + 128*4*4)        // 152896  (128 x 16 f32)
#define SMEM_BYTES (SM_CHI + 128*16*4)       // 161088
// H stage (post-MMA) overlays bytes [0, 128*HSTRIDE*4) = [0, 75776)

// ---- device globals: pre-converted W (bf16 hi/lo, [144][136]) + tail + bias ----
__device__ __align__(16) unsigned char g_Bimg[2 * B_BYTES];
__device__ float g_Wtail[4 * NPAD];
__device__ float g_bias[NPAD];

__device__ __forceinline__ uint32_t smem_u32(const void* p) {
    uint32_t a;
    asm("{ .reg .u64 t; cvta.to.shared.u64 t, %1; cvt.u32.u64 %0, t; }" : "=r"(a) : "l"(p));
    return a;
}
__device__ __forceinline__ void ldm_x4(uint32_t* r, uint32_t addr) {
    asm volatile("ldmatrix.sync.aligned.m8n8.x4.shared.b16 {%0,%1,%2,%3}, [%4];"
                 : "=r"(r[0]), "=r"(r[1]), "=r"(r[2]), "=r"(r[3]) : "r"(addr));
}
__device__ __forceinline__ void ldm_x2(uint32_t* r, uint32_t addr) {
    asm volatile("ldmatrix.sync.aligned.m8n8.x2.shared.b16 {%0,%1}, [%2];"
                 : "=r"(r[0]), "=r"(r[1]) : "r"(addr));
}
__device__ __forceinline__ void mma16816(float* c, const uint32_t* a, const uint32_t* b) {
    asm volatile(
        "mma.sync.aligned.m16n8k16.row.col.f32.bf16.bf16.f32 "
        "{%0,%1,%2,%3}, {%4,%5,%6,%7}, {%8,%9}, {%0,%1,%2,%3};"
        : "+f"(c[0]), "+f"(c[1]), "+f"(c[2]), "+f"(c[3])
        : "r"(a[0]), "r"(a[1]), "r"(a[2]), "r"(a[3]), "r"(b[0]), "r"(b[1]));
}

// ============================================================================
// Prep kernel (once per launch): B[n][k] = W[k][n] split into bf16 hi/lo,
// plus W tail rows (K=128..131) and bias, zero-padded to NPAD cols.
// ============================================================================
__global__ void prep_kernel(const float* __restrict__ W, const float* __restrict__ b) {
    int tid = threadIdx.x;
    for (int idx = tid; idx < NPAD * 128; idx += THREADS) {
        int nrow = idx >> 7;
        int k    = idx & 127;
        float v = (nrow < NCOLS) ? W[k * NCOLS + nrow] : 0.f;
        __nv_bfloat16 hb = __float2bfloat16(v);
        __nv_bfloat16 lb = __float2bfloat16(v - __bfloat162float(hb));
        uint32_t off = (uint32_t)nrow * BSTRIDE_B + (uint32_t)k * 2;
        *(__nv_bfloat16*)(g_Bimg + off) = hb;
        *(__nv_bfloat16*)(g_Bimg + B_BYTES + off) = lb;
    }
    for (int c = tid; c < NPAD; c += THREADS) {
        g_bias[c] = (c < NCOLS) ? b[c] : 0.f;
        #pragma unroll
        for (int s = 0; s < 4; ++s)
            g_Wtail[s * NPAD + c] = (c < NCOLS) ? W[(128 + s) * NCOLS + c] : 0.f;
    }
}

// ============================================================================
// Main kernel
// ============================================================================
__global__ __launch_bounds__(THREADS, 1)
void ib_mma_kernel(const float* __restrict__ x,
                   const float* __restrict__ chi,
                   float* __restrict__ out,
                   int n)
{
    extern __shared__ __align__(16) unsigned char smem[];
    const uint32_t sb = smem_u32(smem);
    const int tid = threadIdx.x;
    const int wid = tid >> 5;
    const int lid = tid & 31;
    const long long row0 = (long long)blockIdx.x * TM;

    // ---- copy pre-converted B image (hi+lo contiguous) into SMEM ----
    {
        const uint4* src = (const uint4*)g_Bimg;
        uint4* dst = (uint4*)(smem + SM_B_HI);
        for (int i = tid; i < (2 * B_BYTES) / 16; i += THREADS) dst[i] = src[i];
        float* wt = (float*)(smem + SM_WT);
        for (int i = tid; i < 4 * NPAD; i += THREADS) wt[i] = g_Wtail[i];
        if (tid < NPAD) ((float*)(smem + SM_BIAS))[tid] = g_bias[tid];
    }

    // ---- stage x tile: split into bf16 hi/lo, row-major [128][136] ----
    #pragma unroll
    for (int it = 0; it < 16; ++it) {
        int i  = tid + THREADS * it;
        int r  = i >> 5;
        int c4 = (i & 31) << 2;
        long long row = row0 + r;
        float4 v = make_float4(0.f, 0.f, 0.f, 0.f);
        if (row < n) v = *(const float4*)(x + row * 128 + c4);
        float vv[4] = {v.x, v.y, v.z, v.w};
        uint16_t hu[4], lu[4];
        #pragma unroll
        for (int q = 0; q < 4; ++q) {
            __nv_bfloat16 hb = __float2bfloat16(vv[q]);
            __nv_bfloat16 lb = __float2bfloat16(vv[q] - __bfloat162float(hb));
            hu[q] = __bfloat16_as_ushort(hb);
            lu[q] = __bfloat16_as_ushort(lb);
        }
        uint32_t off = (uint32_t)r * ASTRIDE_B + (uint32_t)c4 * 2;
        *(uint2*)(smem + SM_A_HI + off) =
            make_uint2((uint32_t)hu[0] | ((uint32_t)hu[1] << 16),
                       (uint32_t)hu[2] | ((uint32_t)hu[3] << 16));
        *(uint2*)(smem + SM_A_LO + off) =
            make_uint2((uint32_t)lu[0] | ((uint32_t)lu[1] << 16),
                       (uint32_t)lu[2] | ((uint32_t)lu[3] << 16));
    }

    // ---- chi stash + d_chi (segment sums of squares) ----
    if (tid < TM) {
        const int r = tid;
        long long row = row0 + r;
        float c[16];
        if (row < n) {
            const float4* cp = (const float4*)(chi + row * 16);
            float4 a0 = cp[0], a1v = cp[1], a2 = cp[2], a3 = cp[3];
            c[0]=a0.x;  c[1]=a0.y;  c[2]=a0.z;  c[3]=a0.w;
            c[4]=a1v.x; c[5]=a1v.y; c[6]=a1v.z; c[7]=a1v.w;
            c[8]=a2.x;  c[9]=a2.y;  c[10]=a2.z; c[11]=a2.w;
            c[12]=a3.x; c[13]=a3.y; c[14]=a3.z; c[15]=a3.w;
        } else {
            #pragma unroll
            for (int m = 0; m < 16; ++m) c[m] = 0.f;
        }
        float* ch = (float*)(smem + SM_CHI);
        #pragma unroll
        for (int m = 0; m < 16; ++m) ch[r * 16 + m] = c[m];
        float* dc = (float*)(smem + SM_DCHI) + r * 4;
        dc[0] = c[0]*c[0];
        dc[1] = c[1]*c[1] + c[2]*c[2] + c[3]*c[3];
        dc[2] = c[4]*c[4] + c[5]*c[5] + c[6]*c[6] + c[7]*c[7] + c[8]*c[8];
        dc[3] = c[9]*c[9] + c[10]*c[10] + c[11]*c[11] + c[12]*c[12]
              + c[13]*c[13] + c[14]*c[14] + c[15]*c[15];
    }
    __syncthreads();

    // ---- warp tiling: 4 row-groups x 2 col-groups ----
    const int m0 = (wid & 3) * 32;            // warp row base (32 rows)
    const int n0 = (wid >> 2) * 72;           // warp col base (72 cols = 9 n8)

    // per-lane ldmatrix source offsets
    const uint32_t a_off = sb + SM_A_HI
        + (uint32_t)(m0 + (lid & 7) + ((lid >> 3) & 1) * 8) * ASTRIDE_B
        + (uint32_t)((lid >> 4) & 1) * 16;                 // kblock select
    const int bl = lid & 15;
    const uint32_t b_off = sb + SM_B_HI
        + (uint32_t)(n0 + (bl & 7)) * BSTRIDE_B
        + (uint32_t)((bl >> 3) & 1) * 16;

    float acc[2][9][4];
    #pragma unroll
    for (int mt = 0; mt < 2; ++mt)
        #pragma unroll
        for (int nt = 0; nt < 9; ++nt)
            #pragma unroll
            for (int q = 0; q < 4; ++q) acc[mt][nt][q] = 0.f;

    #pragma unroll
    for (int k = 0; k < 8; ++k) {
        uint32_t ah[2][4], al[2][4], bh[9][2], blo[9][2];
        #pragma unroll
        for (int mt = 0; mt < 2; ++mt) {
            uint32_t a = a_off + (uint32_t)mt * (16 * ASTRIDE_B) + (uint32_t)k * 32;
            ldm_x4(ah[mt], a);
            ldm_x4(al[mt], a + A_BYTES);
        }
        #pragma unroll
        for (int nt = 0; nt < 9; ++nt) {
            uint32_t a = b_off + (uint32_t)nt * (8 * BSTRIDE_B) + (uint32_t)k * 32;
            ldm_x2(bh[nt], a);
            ldm_x2(blo[nt], a + B_BYTES);
        }
        // pass 1: Ah * Bh   (consecutive MMAs hit distinct accumulators)
        #pragma unroll
        for (int nt = 0; nt < 9; ++nt) {
            mma16816(acc[0][nt], ah[0], bh[nt]);
            mma16816(acc[1][nt], ah[1], bh[nt]);
        }
        // pass 2: Ah * Bl
        #pragma unroll
        for (int nt = 0; nt < 9; ++nt) {
            mma16816(acc[0][nt], ah[0], blo[nt]);
            mma16816(acc[1][nt], ah[1], blo[nt]);
        }
        // pass 3: Al * Bh
        #pragma unroll
        for (int nt = 0; nt < 9; ++nt) {
            mma16816(acc[0][nt], al[0], bh[nt]);
            mma16816(acc[1][nt], al[1], bh[nt]);
        }
    }
    __syncthreads();   // everyone done reading A/B; reuse region as H stage

    // ---- stage raw accumulators to SMEM H [128][HSTRIDE] ----
    {
        float* Hs = (float*)smem;
        const int tr = lid >> 2;
        const int tc = (lid & 3) * 2;
        #pragma unroll
        for (int mt = 0; mt < 2; ++mt) {
            #pragma unroll
            for (int nt = 0; nt < 9; ++nt) {
                int r = m0 + mt * 16 + tr;
                int c = n0 + nt * 8 + tc;
                *(float2*)&Hs[r * HSTRIDE + c] =
                    make_float2(acc[mt][nt][0], acc[mt][nt][1]);
                *(float2*)&Hs[(r + 8) * HSTRIDE + c] =
                    make_float2(acc[mt][nt][2], acc[mt][nt][3]);
            }
        }
    }
    __syncthreads();

    // ---- coalesced stores, applying bias + exact fp32 d_chi tail ----
    const float* Hs = (const float*)smem;
    const float* Bs = (const float*)(smem + SM_BIAS);
    const float* Wt = (const float*)(smem + SM_WT);
    const float* Dc = (const float*)(smem + SM_DCHI);
    const float* Ch = (const float*)(smem + SM_CHI);
    float* out1 = out;
    float* out2 = out + (long long)n * 128;

    #pragma unroll
    for (int it = 0; it < 16; ++it) {
        int i  = tid + THREADS * it;
        int r  = i >> 5;
        int c4 = (i & 31) << 2;
        long long row = row0 + r;
        if (row < n) {
            float4 hv = *(const float4*)&Hs[r * HSTRIDE + c4];
            float4 bi = *(const float4*)&Bs[c4];
            hv.x += bi.x; hv.y += bi.y; hv.z += bi.z; hv.w += bi.w;
            const float* dc = Dc + r * 4;
            #pragma unroll
            for (int s = 0; s < 4; ++s) {
                float4 wv = *(const float4*)&Wt[s * NPAD + c4];
                float d = dc[s];
                hv.x = fmaf(d, wv.x, hv.x);
                hv.y = fmaf(d, wv.y, hv.y);
                hv.z = fmaf(d, wv.z, hv.z);
                hv.w = fmaf(d, wv.w, hv.w);
            }
            *(float4*)(out1 + row * 128 + c4) = hv;
        }
    }
    #pragma unroll
    for (int it = 0; it < 8; ++it) {
        int i = tid + THREADS * it;      // 0..2047
        int r = i >> 4;
        int m = i & 15;
        long long row = row0 + r;
        if (row < n) {
            int s = (m == 0) ? 0 : (m < 4) ? 1 : (m < 9) ? 2 : 3;
            int c = 128 + s;
            const float* dc = Dc + r * 4;
            float h = Hs[r * HSTRIDE + c] + Bs[c];
            #pragma unroll
            for (int q = 0; q < 4; ++q)
                h = fmaf(dc[q], Wt[q * NPAD + c], h);
            out2[row * 16 + m] = h * Ch[r * 16 + m];
        }
    }
}

extern "C" void kernel_launch(void* const* d_in, const int* in_sizes, int n_in,
                              void* d_out, int out_size)
{
    const float* x   = (const float*)d_in[0];
    const float* chi = (const float*)d_in[1];
    // d_in[2] = point_mask (unused by reference computation)
    const float* W   = (const float*)d_in[3];
    const float* b   = (const float*)d_in[4];
    float* out = (float*)d_out;

    const int n = in_sizes[2];

    cudaFuncSetAttribute(ib_mma_kernel,
                         cudaFuncAttributeMaxDynamicSharedMemorySize, SMEM_BYTES);

    prep_kernel<<<1, THREADS>>>(W, b);
    int grid = (n + TM - 1) / TM;
    ib_mma_kernel<<<grid, THREADS, SMEM_BYTES>>>(x, chi, out, n);
}

// round 7
// speedup vs baseline: 2.8381x; 1.7736x over previous
#include <cuda_runtime.h>
#include <cuda_bf16.h>
#include <cstdint>

// InteractionBlock, persistent HMMA kernel with cp.async pipelining.
//   d_chi = segment_sum(chi^2)                          [n,4]
//   h     = x @ W[0:128,:] + d_chi @ W[128:132,:] + b   [n,132]
//   a1      = h[:, :128]        -> out[0 : n*128]
//   chi_out = h[:,128+seg]*chi  -> out[n*128 : n*128+n*16]
//
// GEMM D[128,144] = A[128,128] @ B[144,128]^T, A/B split into bf16 (hi,lo),
// acc = Ah*Bh + Ah*Bl + Al*Bh (fp32). d_chi K-tail applied exactly in fp32.
// Persistent CTAs: B resides in SMEM for the whole kernel; next tile's x/chi
// prefetched via cp.async during current tile's MMA/epilogue.
// Target is plain sm_103 -> mma.sync only (no tcgen05).

#define TM       128
#define NPAD     144
#define NCOLS    132
#define THREADS  256

// 256-byte rows with 16B-chunk XOR swizzle (conflict-free ldmatrix/STS)
#define A_BYTES  (128 * 256)                 // 32768 per image
#define B_BYTES  (NPAD * 256)                // 36864 per image

// ---- SMEM byte layout ----
#define SM_A_HI   0
#define SM_A_LO   32768
#define SM_B_HI   65536
#define SM_B_LO   (65536 + 36864)            // 102400
#define SM_XSTG   139264                     // 128 rows x 512B
#define SM_CSTG   204800                     // 128 rows x 80B (padded)
#define SM_CHI    215040                     // stash 128 x 16 f32
#define SM_DCHI   223232                     // 128 x 4 f32
#define SM_WT2    225280                     // [NPAD][4] f32 (transposed tail)
#define SM_BIAS   227584                     // NPAD f32
#define SM_TAILH  228160                     // 128 x 4 f32 (raw tail accs)
#define SMEM_BYTES 230208

// ---- device globals (built once per launch by prep kernel) ----
__device__ __align__(16) unsigned char g_Bimg[2 * B_BYTES];  // hi then lo
__device__ float g_Wt2[NPAD * 4];   // [c][s]
__device__ float g_bias[NPAD];

__device__ __forceinline__ uint32_t smem_u32(const void* p) {
    uint32_t a;
    asm("{ .reg .u64 t; cvta.to.shared.u64 t, %1; cvt.u32.u64 %0, t; }" : "=r"(a) : "l"(p));
    return a;
}
__device__ __forceinline__ uint32_t swoff(uint32_t r, uint32_t b) {
    // row-major 256B rows, 16B chunk swizzled by low 3 bits of row
    return r * 256u + ((((b >> 4) ^ (r & 7u)) << 4) | (b & 15u));
}
__device__ __forceinline__ void ldm_x4(uint32_t* r, uint32_t addr) {
    asm volatile("ldmatrix.sync.aligned.m8n8.x4.shared.b16 {%0,%1,%2,%3}, [%4];"
                 : "=r"(r[0]), "=r"(r[1]), "=r"(r[2]), "=r"(r[3]) : "r"(addr));
}
__device__ __forceinline__ void ldm_x2(uint32_t* r, uint32_t addr) {
    asm volatile("ldmatrix.sync.aligned.m8n8.x2.shared.b16 {%0,%1}, [%2];"
                 : "=r"(r[0]), "=r"(r[1]) : "r"(addr));
}
__device__ __forceinline__ void mma16816(float* c, const uint32_t* a, const uint32_t* b) {
    asm volatile(
        "mma.sync.aligned.m16n8k16.row.col.f32.bf16.bf16.f32 "
        "{%0,%1,%2,%3}, {%4,%5,%6,%7}, {%8,%9}, {%0,%1,%2,%3};"
        : "+f"(c[0]), "+f"(c[1]), "+f"(c[2]), "+f"(c[3])
        : "r"(a[0]), "r"(a[1]), "r"(a[2]), "r"(a[3]), "r"(b[0]), "r"(b[1]));
}
__device__ __forceinline__ void cp16(uint32_t dst, const void* src, uint32_t bytes) {
    asm volatile("cp.async.cg.shared.global [%0], [%1], 16, %2;"
                 :: "r"(dst), "l"(src), "r"(bytes) : "memory");
}

// ============================================================================
// Prep kernel: swizzled B image (W^T hi/lo), transposed W tail, bias.
// ============================================================================
__global__ void prep_kernel(const float* __restrict__ W, const float* __restrict__ b) {
    int gid = blockIdx.x * blockDim.x + threadIdx.x;
    int nth = gridDim.x * blockDim.x;
    for (int idx = gid; idx < NPAD * 128; idx += nth) {
        int nrow = idx >> 7;
        int k    = idx & 127;
        float v = (nrow < NCOLS) ? W[k * NCOLS + nrow] : 0.f;
        __nv_bfloat16 hb = __float2bfloat16(v);
        __nv_bfloat16 lb = __float2bfloat16(v - __bfloat162float(hb));
        uint32_t off = swoff((uint32_t)nrow, (uint32_t)k * 2);
        *(__nv_bfloat16*)(g_Bimg + off) = hb;
        *(__nv_bfloat16*)(g_Bimg + B_BYTES + off) = lb;
    }
    for (int c = gid; c < NPAD; c += nth) {
        g_bias[c] = (c < NCOLS) ? b[c] : 0.f;
        #pragma unroll
        for (int s = 0; s < 4; ++s)
            g_Wt2[c * 4 + s] = (c < NCOLS) ? W[(128 + s) * NCOLS + c] : 0.f;
    }
}

// ---- prefetch tile t's x and chi into stage buffers ----
__device__ __forceinline__ void prefetch_tile(const float* x, const float* chi,
                                              int n, long long row0,
                                              uint32_t sb, int tid) {
    #pragma unroll
    for (int it = 0; it < 16; ++it) {
        int i   = tid + THREADS * it;
        int r   = i >> 5;
        int c16 = i & 31;
        long long row = row0 + r;
        bool ok = row < n;
        const float* src = x + (ok ? row * 128 : 0) + c16 * 4;
        cp16(sb + SM_XSTG + r * 512 + c16 * 16, src, ok ? 16u : 0u);
    }
    #pragma unroll
    for (int it = 0; it < 2; ++it) {
        int i = tid + THREADS * it;        // 0..511
        int r = i >> 2;
        int q = i & 3;
        long long row = row0 + r;
        bool ok = row < n;
        const float* src = chi + (ok ? row * 16 : 0) + q * 4;
        cp16(sb + SM_CSTG + r * 80 + q * 16, src, ok ? 16u : 0u);
    }
    asm volatile("cp.async.commit_group;" ::: "memory");
}

// ============================================================================
// Main persistent kernel
// ============================================================================
__global__ __launch_bounds__(THREADS, 1)
void ib_pk(const float* __restrict__ x,
           const float* __restrict__ chi,
           float* __restrict__ out,
           int n, int ntiles)
{
    extern __shared__ __align__(16) unsigned char smem[];
    const uint32_t sb = smem_u32(smem);
    const int tid = threadIdx.x;
    const int wid = tid >> 5;
    const int lid = tid & 31;

    int t = blockIdx.x;
    if (t < ntiles)
        prefetch_tile(x, chi, n, (long long)t * TM, sb, tid);
    else
        asm volatile("cp.async.commit_group;" ::: "memory");

    // ---- one-time B image + tail/bias copy (L2-hot) ----
    {
        const uint4* src = (const uint4*)g_Bimg;
        uint4* dst = (uint4*)(smem + SM_B_HI);
        for (int i = tid; i < (2 * B_BYTES) / 16; i += THREADS) dst[i] = src[i];
        float* wt = (float*)(smem + SM_WT2);
        for (int i = tid; i < 4 * NPAD; i += THREADS) wt[i] = g_Wt2[i];
        if (tid < NPAD) ((float*)(smem + SM_BIAS))[tid] = g_bias[tid];
    }

    // warp tiling constants
    const int m0 = (wid & 3) * 32;
    const int n0 = (wid >> 2) * 72;
    const uint32_t rx   = (uint32_t)(lid & 7);
    const uint32_t arow = (uint32_t)(m0 + (lid & 15));
    const uint32_t ahalf = (uint32_t)((lid >> 4) & 1);
    const uint32_t a_base = sb + SM_A_HI + arow * 256;
    const uint32_t nhalf  = (uint32_t)((lid >> 4) & 1);
    const uint32_t khalf  = (uint32_t)((lid >> 3) & 1);
    const uint32_t b_base = sb + SM_B_HI + (uint32_t)(n0 + (int)nhalf * 8 + (lid & 7)) * 256;
    const uint32_t b2_base = sb + SM_B_HI + (uint32_t)(n0 + 64 + (lid & 7)) * 256;
    const int tr = lid >> 2;
    const int tc = (lid & 3) * 2;

    float* out1 = out;
    float* out2 = out + (long long)n * 128;

    while (t < ntiles) {
        const long long row0 = (long long)t * TM;
        asm volatile("cp.async.wait_group 0;" ::: "memory");
        __syncthreads();

        // ---- convert stage -> A hi/lo (swizzled bf16), chi stash + d_chi ----
        #pragma unroll
        for (int it = 0; it < 16; ++it) {
            int i  = tid + THREADS * it;
            int r  = i >> 5;
            int c4 = (i & 31) << 2;
            float4 v = *(const float4*)(smem + SM_XSTG + r * 512 + c4 * 4);
            float vv[4] = {v.x, v.y, v.z, v.w};
            uint16_t hu[4], lu[4];
            #pragma unroll
            for (int q = 0; q < 4; ++q) {
                __nv_bfloat16 hb = __float2bfloat16(vv[q]);
                __nv_bfloat16 lb = __float2bfloat16(vv[q] - __bfloat162float(hb));
                hu[q] = __bfloat16_as_ushort(hb);
                lu[q] = __bfloat16_as_ushort(lb);
            }
            uint32_t off = swoff((uint32_t)r, (uint32_t)c4 * 2);
            *(uint2*)(smem + SM_A_HI + off) =
                make_uint2((uint32_t)hu[0] | ((uint32_t)hu[1] << 16),
                           (uint32_t)hu[2] | ((uint32_t)hu[3] << 16));
            *(uint2*)(smem + SM_A_LO + off) =
                make_uint2((uint32_t)lu[0] | ((uint32_t)lu[1] << 16),
                           (uint32_t)lu[2] | ((uint32_t)lu[3] << 16));
        }
        if (tid < TM) {
            const int r = tid;
            const float* cs = (const float*)(smem + SM_CSTG + r * 80);
            float c[16];
            float4 a0 = ((const float4*)cs)[0], a1v = ((const float4*)cs)[1];
            float4 a2 = ((const float4*)cs)[2], a3 = ((const float4*)cs)[3];
            c[0]=a0.x;  c[1]=a0.y;  c[2]=a0.z;  c[3]=a0.w;
            c[4]=a1v.x; c[5]=a1v.y; c[6]=a1v.z; c[7]=a1v.w;
            c[8]=a2.x;  c[9]=a2.y;  c[10]=a2.z; c[11]=a2.w;
            c[12]=a3.x; c[13]=a3.y; c[14]=a3.z; c[15]=a3.w;
            float* ch = (float*)(smem + SM_CHI);
            #pragma unroll
            for (int m = 0; m < 16; ++m) ch[r * 16 + m] = c[m];
            float* dc = (float*)(smem + SM_DCHI) + r * 4;
            dc[0] = c[0]*c[0];
            dc[1] = c[1]*c[1] + c[2]*c[2] + c[3]*c[3];
            dc[2] = c[4]*c[4] + c[5]*c[5] + c[6]*c[6] + c[7]*c[7] + c[8]*c[8];
            dc[3] = c[9]*c[9] + c[10]*c[10] + c[11]*c[11] + c[12]*c[12]
                  + c[13]*c[13] + c[14]*c[14] + c[15]*c[15];
        }
        __syncthreads();

        // ---- prefetch next tile while MMA/epilogue run ----
        const int tn = t + gridDim.x;
        if (tn < ntiles)
            prefetch_tile(x, chi, n, (long long)tn * TM, sb, tid);
        else
            asm volatile("cp.async.commit_group;" ::: "memory");

        // ---- MMA: 3-term bf16 split ----
        float acc[2][9][4];
        #pragma unroll
        for (int mt = 0; mt < 2; ++mt)
            #pragma unroll
            for (int nt = 0; nt < 9; ++nt)
                #pragma unroll
                for (int q = 0; q < 4; ++q) acc[mt][nt][q] = 0.f;

        #pragma unroll
        for (int k = 0; k < 8; ++k) {
            uint32_t ah[2][4], al[2][4], bh[9][2], bl[9][2];
            const uint32_t ac = (((uint32_t)(2 * k) + ahalf) ^ rx) << 4;
            #pragma unroll
            for (int mt = 0; mt < 2; ++mt) {
                uint32_t a = a_base + (uint32_t)mt * 4096 + ac;
                ldm_x4(ah[mt], a);
                ldm_x4(al[mt], a + (SM_A_LO - SM_A_HI));
            }
            const uint32_t bc = (((uint32_t)(2 * k) + khalf) ^ rx) << 4;
            #pragma unroll
            for (int p = 0; p < 4; ++p) {
                uint32_t a = b_base + (uint32_t)p * 4096 + bc;
                uint32_t r4[4];
                ldm_x4(r4, a);
                bh[2*p][0] = r4[0]; bh[2*p][1] = r4[1];
                bh[2*p+1][0] = r4[2]; bh[2*p+1][1] = r4[3];
                ldm_x4(r4, a + (SM_B_LO - SM_B_HI));
                bl[2*p][0] = r4[0]; bl[2*p][1] = r4[1];
                bl[2*p+1][0] = r4[2]; bl[2*p+1][1] = r4[3];
            }
            {
                uint32_t a2a = b2_base + bc;
                ldm_x2(bh[8], a2a);
                ldm_x2(bl[8], a2a + (SM_B_LO - SM_B_HI));
            }
            #pragma unroll
            for (int nt = 0; nt < 9; ++nt) {
                mma16816(acc[0][nt], ah[0], bh[nt]);
                mma16816(acc[1][nt], ah[1], bh[nt]);
            }
            #pragma unroll
            for (int nt = 0; nt < 9; ++nt) {
                mma16816(acc[0][nt], ah[0], bl[nt]);
                mma16816(acc[1][nt], ah[1], bl[nt]);
            }
            #pragma unroll
            for (int nt = 0; nt < 9; ++nt) {
                mma16816(acc[0][nt], al[0], bh[nt]);
                mma16816(acc[1][nt], al[1], bh[nt]);
            }
        }

        // ---- epilogue: direct a1 stores (bias + exact d_chi tail), tail->smem ----
        const float* Bs  = (const float*)(smem + SM_BIAS);
        const float* Wt2 = (const float*)(smem + SM_WT2);
        const float* Dc  = (const float*)(smem + SM_DCHI);
        float* Th = (float*)(smem + SM_TAILH);

        #pragma unroll
        for (int mt = 0; mt < 2; ++mt) {
            const int r = m0 + mt * 16 + tr;
            const long long rowA = row0 + r;
            const long long rowB = rowA + 8;
            const float4 dca = *(const float4*)&Dc[r * 4];
            const float4 dcb = *(const float4*)&Dc[(r + 8) * 4];
            #pragma unroll
            for (int nt = 0; nt < 9; ++nt) {
                const int c = n0 + nt * 8 + tc;
                if (c < 128) {
                    float2 bi = *(const float2*)&Bs[c];
                    float4 w0 = *(const float4*)&Wt2[c * 4];
                    float4 w1 = *(const float4*)&Wt2[(c + 1) * 4];
                    float h0 = acc[mt][nt][0] + bi.x;
                    float h1 = acc[mt][nt][1] + bi.y;
                    float h2 = acc[mt][nt][2] + bi.x;
                    float h3 = acc[mt][nt][3] + bi.y;
                    h0 = fmaf(dca.x, w0.x, h0); h0 = fmaf(dca.y, w0.y, h0);
                    h0 = fmaf(dca.z, w0.z, h0); h0 = fmaf(dca.w, w0.w, h0);
                    h1 = fmaf(dca.x, w1.x, h1); h1 = fmaf(dca.y, w1.y, h1);
                    h1 = fmaf(dca.z, w1.z, h1); h1 = fmaf(dca.w, w1.w, h1);
                    h2 = fmaf(dcb.x, w0.x, h2); h2 = fmaf(dcb.y, w0.y, h2);
                    h2 = fmaf(dcb.z, w0.z, h2); h2 = fmaf(dcb.w, w0.w, h2);
                    h3 = fmaf(dcb.x, w1.x, h3); h3 = fmaf(dcb.y, w1.y, h3);
                    h3 = fmaf(dcb.z, w1.z, h3); h3 = fmaf(dcb.w, w1.w, h3);
                    if (rowA < n) *(float2*)(out1 + rowA * 128 + c) = make_float2(h0, h1);
                    if (rowB < n) *(float2*)(out1 + rowB * 128 + c) = make_float2(h2, h3);
                } else if (c < 132) {
                    Th[r * 4 + (c - 128)]       = acc[mt][nt][0];
                    Th[r * 4 + (c - 127)]       = acc[mt][nt][1];
                    Th[(r + 8) * 4 + (c - 128)] = acc[mt][nt][2];
                    Th[(r + 8) * 4 + (c - 127)] = acc[mt][nt][3];
                }
            }
        }
        __syncthreads();

        // ---- chi_out ----
        {
            const float* Ch = (const float*)(smem + SM_CHI);
            #pragma unroll
            for (int it = 0; it < 8; ++it) {
                int i = tid + THREADS * it;     // 0..2047
                int r = i >> 4;
                int m = i & 15;
                long long row = row0 + r;
                if (row < n) {
                    int s = (m == 0) ? 0 : (m < 4) ? 1 : (m < 9) ? 2 : 3;
                    const float4 dc = *(const float4*)&Dc[r * 4];
                    const float4 w  = *(const float4*)&Wt2[(128 + s) * 4];
                    float h = Th[r * 4 + s] + Bs[128 + s];
                    h = fmaf(dc.x, w.x, h); h = fmaf(dc.y, w.y, h);
                    h = fmaf(dc.z, w.z, h); h = fmaf(dc.w, w.w, h);
                    out2[row * 16 + m] = h * Ch[r * 16 + m];
                }
            }
        }
        t = tn;
    }
}

extern "C" void kernel_launch(void* const* d_in, const int* in_sizes, int n_in,
                              void* d_out, int out_size)
{
    const float* x   = (const float*)d_in[0];
    const float* chi = (const float*)d_in[1];
    // d_in[2] = point_mask (unused by reference computation)
    const float* W   = (const float*)d_in[3];
    const float* b   = (const float*)d_in[4];
    float* out = (float*)d_out;

    const int n = in_sizes[2];
    const int ntiles = (n + TM - 1) / TM;

    int dev = 0, nsm = 148;
    cudaGetDevice(&dev);
    cudaDeviceGetAttribute(&nsm, cudaDevAttrMultiProcessorCount, dev);

    cudaFuncSetAttribute(ib_pk,
                         cudaFuncAttributeMaxDynamicSharedMemorySize, SMEM_BYTES);

    prep_kernel<<<64, THREADS>>>(W, b);
    int grid = ntiles < nsm ? ntiles : nsm;
    ib_pk<<<grid, THREADS, SMEM_BYTES>>>(x, chi, out, n, ntiles);
}